// round 1
// baseline (speedup 1.0000x reference)
#include <cuda_runtime.h>
#include <cstddef>

// ---------------------------------------------------------------------------
// DiffJPEG: per 8x8 block  ->  D X D^T  ->  round(x/Q)*Q  ->  D^T X' D
// Input/Output: (32, 3, 512, 512) float32, contiguous.
// One thread processes one full 8x8 block. All matrix constants are
// compile-time literals so ptxas can use the full-rate FFMA-imm form.
// ---------------------------------------------------------------------------

// cos(m*pi/16) table, m in [0,8]
__host__ __device__ constexpr float COS9(int m) {
    constexpr float t[9] = {
        1.0f,
        0.9807852804032304f,
        0.9238795325112868f,
        0.8314696123025452f,
        0.7071067811865476f,
        0.5555702330196022f,
        0.3826834323650898f,
        0.1950903220161283f,
        0.0f
    };
    return t[m];
}

__host__ __device__ constexpr float cos16f(int m) {
    m &= 31;
    if (m <= 8)  return  COS9(m);
    if (m <= 16) return -COS9(16 - m);
    if (m <= 24) return -COS9(m - 16);
    return COS9(32 - m);
}

struct Mat8 { float v[8][8]; };

__host__ __device__ constexpr Mat8 makeD() {
    Mat8 d{};
    for (int i = 0; i < 8; i++)
        for (int j = 0; j < 8; j++)
            d.v[i][j] = (i == 0 ? 0.35355339059327373f : 0.5f) * cos16f((2 * j + 1) * i);
    return d;
}

// quality=50 -> scale=100 -> floor((q*100+50)/100) = q exactly (integer table)
__host__ __device__ constexpr Mat8 makeQ() {
    Mat8 q{};
    constexpr float t[8][8] = {
        {16, 11, 10, 16, 24, 40, 51, 61},
        {12, 12, 14, 19, 26, 58, 60, 55},
        {14, 13, 16, 24, 40, 57, 69, 56},
        {14, 17, 22, 29, 51, 87, 80, 62},
        {18, 22, 37, 56, 68, 109, 103, 77},
        {24, 35, 55, 64, 81, 104, 113, 92},
        {49, 64, 78, 87, 103, 121, 120, 101},
        {72, 92, 95, 98, 112, 100, 103, 99}};
    for (int i = 0; i < 8; i++)
        for (int j = 0; j < 8; j++)
            q.v[i][j] = t[i][j];
    return q;
}

__host__ __device__ constexpr Mat8 makeQinv() {
    Mat8 qi{};
    constexpr Mat8 q = makeQ();
    for (int i = 0; i < 8; i++)
        for (int j = 0; j < 8; j++)
            qi.v[i][j] = 1.0f / q.v[i][j];
    return qi;
}

// Image geometry (fixed by the problem)
constexpr int W      = 512;
constexpr int H      = 512;
constexpr int BW     = W / 8;               // 64 blocks per row
constexpr int BLKS_PER_IMG = (H / 8) * BW;  // 4096
constexpr int IMG_ELEMS    = H * W;         // 262144

__global__ void __launch_bounds__(256)
diffjpeg_kernel(const float* __restrict__ in, float* __restrict__ out, int nblocks) {
    constexpr Mat8 D  = makeD();
    constexpr Mat8 Q  = makeQ();
    constexpr Mat8 Qi = makeQinv();

    int t = blockIdx.x * 256 + threadIdx.x;
    if (t >= nblocks) return;

    int img = t >> 12;          // / 4096
    int rem = t & 4095;
    int br  = rem >> 6;         // block row
    int bc  = rem & 63;         // block col

    size_t base = (size_t)img * IMG_ELEMS + (size_t)br * 8 * W + (size_t)bc * 8;
    const float* src = in + base;
    float* dst = out + base;

    // T = D * X * D^T, accumulated streaming over input rows.
    float T[8][8];
    #pragma unroll
    for (int i = 0; i < 8; i++)
        #pragma unroll
        for (int j = 0; j < 8; j++)
            T[i][j] = 0.0f;

    #pragma unroll
    for (int r = 0; r < 8; r++) {
        float4 a = *reinterpret_cast<const float4*>(src + (size_t)r * W);
        float4 b = *reinterpret_cast<const float4*>(src + (size_t)r * W + 4);
        float x[8] = {a.x, a.y, a.z, a.w, b.x, b.y, b.z, b.w};

        // u[j] = sum_c x[c] * D[j][c]   (row projected onto DCT basis)
        float u[8];
        #pragma unroll
        for (int j = 0; j < 8; j++) {
            float s = x[0] * D.v[j][0];
            #pragma unroll
            for (int c = 1; c < 8; c++)
                s += x[c] * D.v[j][c];   // FFMA with immediate multiplier
            u[j] = s;
        }
        // T[i][j] += u[j] * D[i][r]     (immediate multiplier again)
        #pragma unroll
        for (int i = 0; i < 8; i++)
            #pragma unroll
            for (int j = 0; j < 8; j++)
                T[i][j] += u[j] * D.v[i][r];
    }

    // Quantize with straight-through rounding: T' = round(T / Q) * Q
    #pragma unroll
    for (int i = 0; i < 8; i++)
        #pragma unroll
        for (int j = 0; j < 8; j++)
            T[i][j] = rintf(T[i][j] * Qi.v[i][j]) * Q.v[i][j];

    // Y = D^T * T' * D, streamed per output row k.
    #pragma unroll
    for (int k = 0; k < 8; k++) {
        // v[l] = sum_i T'[i][l] * D[i][k]
        float v[8];
        #pragma unroll
        for (int l = 0; l < 8; l++) {
            float s = T[0][l] * D.v[0][k];
            #pragma unroll
            for (int i = 1; i < 8; i++)
                s += T[i][l] * D.v[i][k];
            v[l] = s;
        }
        // y[j] = sum_l v[l] * D[l][j]
        float y[8];
        #pragma unroll
        for (int j = 0; j < 8; j++) {
            float s = v[0] * D.v[0][j];
            #pragma unroll
            for (int l = 1; l < 8; l++)
                s += v[l] * D.v[l][j];
            y[j] = s;
        }
        float4 a = make_float4(y[0], y[1], y[2], y[3]);
        float4 b = make_float4(y[4], y[5], y[6], y[7]);
        *reinterpret_cast<float4*>(dst + (size_t)k * W)     = a;
        *reinterpret_cast<float4*>(dst + (size_t)k * W + 4) = b;
    }
}

extern "C" void kernel_launch(void* const* d_in, const int* in_sizes, int n_in,
                              void* d_out, int out_size) {
    const float* in = (const float*)d_in[0];
    float* out = (float*)d_out;
    int nblocks = in_sizes[0] / 64;   // 393216 for (32,3,512,512)
    int grid = (nblocks + 255) / 256;
    diffjpeg_kernel<<<grid, 256>>>(in, out, nblocks);
}

// round 2
// speedup vs baseline: 1.1952x; 1.1952x over previous
#include <cuda_runtime.h>
#include <cstddef>

// ---------------------------------------------------------------------------
// DiffJPEG: per 8x8 block  ->  D X D^T  ->  round(x/Q)*Q  ->  D^T X' D
// Input/Output: (32, 3, 512, 512) float32, contiguous.
// One thread per 8x8 block. Even/odd DCT symmetry (8-pt transform = 8 add +
// 32 imm-FFMA) + exact round-half-even via the 1.5*2^23 magic constant.
// All matrix constants are compile-time literals -> FFMA-imm (rt=1).
// ---------------------------------------------------------------------------

__host__ __device__ constexpr float COS9(int m) {
    constexpr float t[9] = {
        1.0f,
        0.9807852804032304f,
        0.9238795325112868f,
        0.8314696123025452f,
        0.7071067811865476f,
        0.5555702330196022f,
        0.3826834323650898f,
        0.1950903220161283f,
        0.0f
    };
    return t[m];
}

__host__ __device__ constexpr float cos16f(int m) {
    m &= 31;
    if (m <= 8)  return  COS9(m);
    if (m <= 16) return -COS9(16 - m);
    if (m <= 24) return -COS9(m - 16);
    return COS9(32 - m);
}

struct Mat8 { float v[8][8]; };
struct Mat4 { float v[4][4]; };

__host__ __device__ constexpr Mat8 makeD() {
    Mat8 d{};
    for (int i = 0; i < 8; i++)
        for (int j = 0; j < 8; j++)
            d.v[i][j] = (i == 0 ? 0.35355339059327373f : 0.5f) * cos16f((2 * j + 1) * i);
    return d;
}

// Even rows of D (i = 0,2,4,6), first 4 columns
__host__ __device__ constexpr Mat4 makeE() {
    Mat4 e{};
    constexpr Mat8 d = makeD();
    for (int k = 0; k < 4; k++)
        for (int j = 0; j < 4; j++)
            e.v[k][j] = d.v[2 * k][j];
    return e;
}
// Odd rows of D (i = 1,3,5,7), first 4 columns
__host__ __device__ constexpr Mat4 makeO() {
    Mat4 o{};
    constexpr Mat8 d = makeD();
    for (int k = 0; k < 4; k++)
        for (int j = 0; j < 4; j++)
            o.v[k][j] = d.v[2 * k + 1][j];
    return o;
}

// quality=50 -> scale=100 -> Q is exactly the integer luma table
__host__ __device__ constexpr Mat8 makeQ() {
    Mat8 q{};
    constexpr float t[8][8] = {
        {16, 11, 10, 16, 24, 40, 51, 61},
        {12, 12, 14, 19, 26, 58, 60, 55},
        {14, 13, 16, 24, 40, 57, 69, 56},
        {14, 17, 22, 29, 51, 87, 80, 62},
        {18, 22, 37, 56, 68, 109, 103, 77},
        {24, 35, 55, 64, 81, 104, 113, 92},
        {49, 64, 78, 87, 103, 121, 120, 101},
        {72, 92, 95, 98, 112, 100, 103, 99}};
    for (int i = 0; i < 8; i++)
        for (int j = 0; j < 8; j++)
            q.v[i][j] = t[i][j];
    return q;
}

__host__ __device__ constexpr Mat8 makeQinv() {
    Mat8 qi{};
    constexpr Mat8 q = makeQ();
    for (int i = 0; i < 8; i++)
        for (int j = 0; j < 8; j++)
            qi.v[i][j] = 1.0f / q.v[i][j];
    return qi;
}

constexpr int W            = 512;
constexpr int H            = 512;
constexpr int IMG_ELEMS    = H * W;       // 262144
constexpr float RMAGIC     = 12582912.0f; // 1.5 * 2^23 : round-half-even magic

// Forward 8-point DCT-II (orthonormal) via even/odd decomposition.
// out[i] = sum_j D[i][j] in[j]
__device__ __forceinline__ void dct8_fwd(const float in[8], float out[8]) {
    constexpr Mat4 E = makeE();
    constexpr Mat4 O = makeO();
    float s[4], d[4];
    #pragma unroll
    for (int j = 0; j < 4; j++) {
        s[j] = in[j] + in[7 - j];
        d[j] = in[j] - in[7 - j];
    }
    #pragma unroll
    for (int k = 0; k < 4; k++) {
        float se = s[0] * E.v[k][0];
        float so = d[0] * O.v[k][0];
        #pragma unroll
        for (int j = 1; j < 4; j++) {
            se += s[j] * E.v[k][j];
            so += d[j] * O.v[k][j];
        }
        out[2 * k]     = se;
        out[2 * k + 1] = so;
    }
}

// Inverse: out[j] = sum_i D[i][j] in[i]
__device__ __forceinline__ void dct8_inv(const float in[8], float out[8]) {
    constexpr Mat4 E = makeE();
    constexpr Mat4 O = makeO();
    #pragma unroll
    for (int j = 0; j < 4; j++) {
        float e = in[0] * E.v[0][j];
        float o = in[1] * O.v[0][j];
        #pragma unroll
        for (int k = 1; k < 4; k++) {
            e += in[2 * k]     * E.v[k][j];
            o += in[2 * k + 1] * O.v[k][j];
        }
        out[j]     = e + o;
        out[7 - j] = e - o;
    }
}

__global__ void __launch_bounds__(256)
diffjpeg_kernel(const float* __restrict__ in, float* __restrict__ out, int nblocks) {
    constexpr Mat8 Q  = makeQ();
    constexpr Mat8 Qi = makeQinv();

    int t = blockIdx.x * 256 + threadIdx.x;
    if (t >= nblocks) return;

    int img = t >> 12;          // / 4096 blocks per image
    int rem = t & 4095;
    int br  = rem >> 6;         // block row
    int bc  = rem & 63;         // block col

    size_t base = (size_t)img * IMG_ELEMS + (size_t)br * 8 * W + (size_t)bc * 8;
    const float* src = in + base;
    float* dst = out + base;

    float T[8][8];

    // Row transform: T[r][j] = sum_c D[j][c] X[r][c]
    #pragma unroll
    for (int r = 0; r < 8; r++) {
        float4 a = *reinterpret_cast<const float4*>(src + (size_t)r * W);
        float4 b = *reinterpret_cast<const float4*>(src + (size_t)r * W + 4);
        float x[8] = {a.x, a.y, a.z, a.w, b.x, b.y, b.z, b.w};
        float u[8];
        dct8_fwd(x, u);
        #pragma unroll
        for (int j = 0; j < 8; j++) T[r][j] = u[j];
    }

    // Column transform + quantize + column inverse, per column j.
    #pragma unroll
    for (int j = 0; j < 8; j++) {
        float col[8], f[8];
        #pragma unroll
        for (int r = 0; r < 8; r++) col[r] = T[r][j];
        dct8_fwd(col, f);              // f[i] = (D X D^T)[i][j]
        // quantize: round-half-even(f*Qi)*Q, exact rintf semantics for |p|<2^22
        #pragma unroll
        for (int i = 0; i < 8; i++) {
            float p = f[i] * Qi.v[i][j];
            float r1 = __fadd_rn(p, RMAGIC);
            float r2 = __fadd_rn(r1, -RMAGIC);
            f[i] = r2 * Q.v[i][j];
        }
        dct8_inv(f, col);              // col[r] = sum_i D[i][r] f[i]
        #pragma unroll
        for (int r = 0; r < 8; r++) T[r][j] = col[r];
    }

    // Row inverse + store: Y[r][c] = sum_l D[l][c] M[r][l]
    #pragma unroll
    for (int r = 0; r < 8; r++) {
        float y[8];
        dct8_inv(T[r], y);
        *reinterpret_cast<float4*>(dst + (size_t)r * W)     = make_float4(y[0], y[1], y[2], y[3]);
        *reinterpret_cast<float4*>(dst + (size_t)r * W + 4) = make_float4(y[4], y[5], y[6], y[7]);
    }
}

extern "C" void kernel_launch(void* const* d_in, const int* in_sizes, int n_in,
                              void* d_out, int out_size) {
    const float* in = (const float*)d_in[0];
    float* out = (float*)d_out;
    int nblocks = in_sizes[0] / 64;   // 393216
    int grid = (nblocks + 255) / 256;
    diffjpeg_kernel<<<grid, 256>>>(in, out, nblocks);
}

// round 3
// speedup vs baseline: 1.3754x; 1.1508x over previous
#include <cuda_runtime.h>
#include <cstddef>

// ---------------------------------------------------------------------------
// DiffJPEG: per 8x8 block  ->  D X D^T  ->  round(x/Q)*Q  ->  D^T X' D
// Input/Output: (32, 3, 512, 512) float32, contiguous.
// One thread per 8x8 block. Even/odd DCT symmetry + magic-constant
// round-half-even. Register cap (__launch_bounds__ 256,3) to lift occupancy
// from 2 to 3 CTAs/SM: round-2 ncu showed issue=49.6%/occ=20% (latency-bound).
// ---------------------------------------------------------------------------

__host__ __device__ constexpr float COS9(int m) {
    constexpr float t[9] = {
        1.0f,
        0.9807852804032304f,
        0.9238795325112868f,
        0.8314696123025452f,
        0.7071067811865476f,
        0.5555702330196022f,
        0.3826834323650898f,
        0.1950903220161283f,
        0.0f
    };
    return t[m];
}

__host__ __device__ constexpr float cos16f(int m) {
    m &= 31;
    if (m <= 8)  return  COS9(m);
    if (m <= 16) return -COS9(16 - m);
    if (m <= 24) return -COS9(m - 16);
    return COS9(32 - m);
}

struct Mat8 { float v[8][8]; };
struct Mat4 { float v[4][4]; };

__host__ __device__ constexpr Mat8 makeD() {
    Mat8 d{};
    for (int i = 0; i < 8; i++)
        for (int j = 0; j < 8; j++)
            d.v[i][j] = (i == 0 ? 0.35355339059327373f : 0.5f) * cos16f((2 * j + 1) * i);
    return d;
}

// Even rows of D (i = 0,2,4,6), first 4 columns
__host__ __device__ constexpr Mat4 makeE() {
    Mat4 e{};
    constexpr Mat8 d = makeD();
    for (int k = 0; k < 4; k++)
        for (int j = 0; j < 4; j++)
            e.v[k][j] = d.v[2 * k][j];
    return e;
}
// Odd rows of D (i = 1,3,5,7), first 4 columns
__host__ __device__ constexpr Mat4 makeO() {
    Mat4 o{};
    constexpr Mat8 d = makeD();
    for (int k = 0; k < 4; k++)
        for (int j = 0; j < 4; j++)
            o.v[k][j] = d.v[2 * k + 1][j];
    return o;
}

// quality=50 -> scale=100 -> Q is exactly the integer luma table
__host__ __device__ constexpr Mat8 makeQ() {
    Mat8 q{};
    constexpr float t[8][8] = {
        {16, 11, 10, 16, 24, 40, 51, 61},
        {12, 12, 14, 19, 26, 58, 60, 55},
        {14, 13, 16, 24, 40, 57, 69, 56},
        {14, 17, 22, 29, 51, 87, 80, 62},
        {18, 22, 37, 56, 68, 109, 103, 77},
        {24, 35, 55, 64, 81, 104, 113, 92},
        {49, 64, 78, 87, 103, 121, 120, 101},
        {72, 92, 95, 98, 112, 100, 103, 99}};
    for (int i = 0; i < 8; i++)
        for (int j = 0; j < 8; j++)
            q.v[i][j] = t[i][j];
    return q;
}

__host__ __device__ constexpr Mat8 makeQinv() {
    Mat8 qi{};
    constexpr Mat8 q = makeQ();
    for (int i = 0; i < 8; i++)
        for (int j = 0; j < 8; j++)
            qi.v[i][j] = 1.0f / q.v[i][j];
    return qi;
}

constexpr int W            = 512;
constexpr int H            = 512;
constexpr int IMG_ELEMS    = H * W;       // 262144
constexpr float RMAGIC     = 12582912.0f; // 1.5 * 2^23 : round-half-even magic

// Forward 8-point DCT-II (orthonormal) via even/odd decomposition.
__device__ __forceinline__ void dct8_fwd(const float in[8], float out[8]) {
    constexpr Mat4 E = makeE();
    constexpr Mat4 O = makeO();
    float s[4], d[4];
    #pragma unroll
    for (int j = 0; j < 4; j++) {
        s[j] = in[j] + in[7 - j];
        d[j] = in[j] - in[7 - j];
    }
    #pragma unroll
    for (int k = 0; k < 4; k++) {
        float se = s[0] * E.v[k][0];
        float so = d[0] * O.v[k][0];
        #pragma unroll
        for (int j = 1; j < 4; j++) {
            se += s[j] * E.v[k][j];
            so += d[j] * O.v[k][j];
        }
        out[2 * k]     = se;
        out[2 * k + 1] = so;
    }
}

// Inverse: out[j] = sum_i D[i][j] in[i]
__device__ __forceinline__ void dct8_inv(const float in[8], float out[8]) {
    constexpr Mat4 E = makeE();
    constexpr Mat4 O = makeO();
    #pragma unroll
    for (int j = 0; j < 4; j++) {
        float e = in[0] * E.v[0][j];
        float o = in[1] * O.v[0][j];
        #pragma unroll
        for (int k = 1; k < 4; k++) {
            e += in[2 * k]     * E.v[k][j];
            o += in[2 * k + 1] * O.v[k][j];
        }
        out[j]     = e + o;
        out[7 - j] = e - o;
    }
}

__global__ void __launch_bounds__(256, 3)
diffjpeg_kernel(const float* __restrict__ in, float* __restrict__ out, int nblocks) {
    constexpr Mat8 Q  = makeQ();
    constexpr Mat8 Qi = makeQinv();

    int t = blockIdx.x * 256 + threadIdx.x;
    if (t >= nblocks) return;

    int img = t >> 12;          // / 4096 blocks per image
    int rem = t & 4095;
    int br  = rem >> 6;         // block row
    int bc  = rem & 63;         // block col

    size_t base = (size_t)img * IMG_ELEMS + (size_t)br * 8 * W + (size_t)bc * 8;
    const float* src = in + base;
    float* dst = out + base;

    float T[8][8];

    // Row transform: T[r][j] = sum_c D[j][c] X[r][c]
    #pragma unroll
    for (int r = 0; r < 8; r++) {
        float4 a = *reinterpret_cast<const float4*>(src + (size_t)r * W);
        float4 b = *reinterpret_cast<const float4*>(src + (size_t)r * W + 4);
        float x[8] = {a.x, a.y, a.z, a.w, b.x, b.y, b.z, b.w};
        float u[8];
        dct8_fwd(x, u);
        #pragma unroll
        for (int j = 0; j < 8; j++) T[r][j] = u[j];
    }

    // Column transform + quantize + column inverse, per column j.
    #pragma unroll
    for (int j = 0; j < 8; j++) {
        float col[8], f[8];
        #pragma unroll
        for (int r = 0; r < 8; r++) col[r] = T[r][j];
        dct8_fwd(col, f);              // f[i] = (D X D^T)[i][j]
        // quantize: round-half-even(f*Qi)*Q, exact rintf semantics for |p|<2^22
        #pragma unroll
        for (int i = 0; i < 8; i++) {
            float p = f[i] * Qi.v[i][j];
            float r1 = __fadd_rn(p, RMAGIC);
            float r2 = __fadd_rn(r1, -RMAGIC);
            f[i] = r2 * Q.v[i][j];
        }
        dct8_inv(f, col);              // col[r] = sum_i D[i][r] f[i]
        #pragma unroll
        for (int r = 0; r < 8; r++) T[r][j] = col[r];
    }

    // Row inverse + store: Y[r][c] = sum_l D[l][c] M[r][l]
    #pragma unroll
    for (int r = 0; r < 8; r++) {
        float y[8];
        dct8_inv(T[r], y);
        *reinterpret_cast<float4*>(dst + (size_t)r * W)     = make_float4(y[0], y[1], y[2], y[3]);
        *reinterpret_cast<float4*>(dst + (size_t)r * W + 4) = make_float4(y[4], y[5], y[6], y[7]);
    }
}

extern "C" void kernel_launch(void* const* d_in, const int* in_sizes, int n_in,
                              void* d_out, int out_size) {
    const float* in = (const float*)d_in[0];
    float* out = (float*)d_out;
    int nblocks = in_sizes[0] / 64;   // 393216
    int grid = (nblocks + 255) / 256;
    diffjpeg_kernel<<<grid, 256>>>(in, out, nblocks);
}